// round 13
// baseline (speedup 1.0000x reference)
#include <cuda_runtime.h>
#include <cuda_fp16.h>
#include <math.h>
#include <stdint.h>

// ---------------- problem constants ----------------
#define B_  2
#define S_  2048
#define E_  1024
#define H_  16
#define HD_ 64
#define FF_ 4096
#define M_  (B_ * S_)          // 4096 rows

// Q pre-scale: (1/sqrt(64)) * log2(e)
#define QSCALE_F 0.1803368801111244f

// ---------------- fp32 scratch ----------------
__device__ __align__(128) float g_tmp[(size_t)M_ * E_];
__device__ __align__(128) float g_x1 [(size_t)M_ * E_];

// ---------------- fp16 scratch ----------------
__device__ __align__(128) __half g_xh   [(size_t)M_ * E_];
__device__ __align__(128) __half g_qkvh [(size_t)M_ * 3 * E_], g_qkvl [(size_t)M_ * 3 * E_];
__device__ __align__(128) __half g_ctxh [(size_t)M_ * E_];
__device__ __align__(128) __half g_x1h  [(size_t)M_ * E_];
__device__ __align__(128) __half g_hh   [(size_t)M_ * FF_];
__device__ __align__(128) __half g_wqkvh[(size_t)3 * E_ * E_];
__device__ __align__(128) __half g_wouth[(size_t)E_ * E_];
__device__ __align__(128) __half g_w1h  [(size_t)FF_ * E_];
__device__ __align__(128) __half g_w2h  [(size_t)E_ * FF_];

// ============================================================================
// helpers
// ============================================================================
__device__ __forceinline__ uint32_t smem_u32(const void* p) {
    uint32_t a;
    asm("{ .reg .u64 t; cvta.to.shared.u64 t, %1; cvt.u32.u64 %0, t; }"
        : "=r"(a) : "l"(p));
    return a;
}

__device__ __forceinline__ void cp16(uint32_t dst, const void* src) {
    asm volatile("cp.async.cg.shared.global [%0], [%1], 16;"
                 :: "r"(dst), "l"(src) : "memory");
}
#define CP_COMMIT()  asm volatile("cp.async.commit_group;" ::: "memory")
#define CP_WAIT(N)   asm volatile("cp.async.wait_group %0;" :: "n"(N) : "memory")

__device__ __forceinline__ void ldsm4(uint32_t* r, uint32_t addr) {
    asm volatile("ldmatrix.sync.aligned.m8n8.x4.shared.b16 {%0,%1,%2,%3}, [%4];"
                 : "=r"(r[0]), "=r"(r[1]), "=r"(r[2]), "=r"(r[3]) : "r"(addr));
}
__device__ __forceinline__ void ldsm4t(uint32_t* r, uint32_t addr) {
    asm volatile("ldmatrix.sync.aligned.m8n8.x4.trans.shared.b16 {%0,%1,%2,%3}, [%4];"
                 : "=r"(r[0]), "=r"(r[1]), "=r"(r[2]), "=r"(r[3]) : "r"(addr));
}

__device__ __forceinline__ void mma16816(float d[4], const uint32_t a[4],
                                         uint32_t b0, uint32_t b1) {
    asm volatile(
        "mma.sync.aligned.m16n8k16.row.col.f32.f16.f16.f32 "
        "{%0,%1,%2,%3}, {%4,%5,%6,%7}, {%8,%9}, {%0,%1,%2,%3};"
        : "+f"(d[0]), "+f"(d[1]), "+f"(d[2]), "+f"(d[3])
        : "r"(a[0]), "r"(a[1]), "r"(a[2]), "r"(a[3]), "r"(b0), "r"(b1));
}

__device__ __forceinline__ void split2h(float v, __half& h, __half& l) {
    h = __float2half_rn(v);
    l = __float2half_rn(v - __half2float(h));
}
__device__ __forceinline__ uint32_t packh2(__half a, __half b) {
    __half2 t; t.x = a; t.y = b;
    return *(uint32_t*)&t;
}

// ============================================================================
// Fused fp32 -> fp16 convert: 4 weights + x in one launch (16384 blocks).
// ============================================================================
__global__ __launch_bounds__(256)
void conv_kernel(const float* __restrict__ s0, const float* __restrict__ s1,
                 const float* __restrict__ s2, const float* __restrict__ s3,
                 const float* __restrict__ s4,
                 __half* __restrict__ d0, __half* __restrict__ d1,
                 __half* __restrict__ d2, __half* __restrict__ d3,
                 __half* __restrict__ d4) {
    const int b = blockIdx.x;
    const float* s; __half* d; int base;
    if      (b < 3072)  { s = s0; d = d0; base = b; }
    else if (b < 4096)  { s = s1; d = d1; base = b - 3072; }
    else if (b < 8192)  { s = s2; d = d2; base = b - 4096; }
    else if (b < 12288) { s = s3; d = d3; base = b - 8192; }
    else                { s = s4; d = d4; base = b - 12288; }
    const int i = base * 256 + threadIdx.x;
    float4 v = ((const float4*)s)[i];
    ((__half2*)d)[2 * i]     = __floats2half2_rn(v.x, v.y);
    ((__half2*)d)[2 * i + 1] = __floats2half2_rn(v.z, v.w);
}

// ============================================================================
// mma.sync HGEMM v3: C = A[M,K] @ B[N,K]^T + bias.
// CTA tile 128(M) x 256(N), K-tile 32, 8 warps (2M x 4N), warp tile 64x64.
// 4-stage cp.async, 1 CTA/SM (acc = 128 regs).  Cuts smem bytes/MMA ~35%.
// ACT: 0/1 GELU.  OUT: 0 fp32, 1 fp16 hi+lo, 2 fp16 hi only.
// SCALEQ: Q columns ((n%192)<64) scaled by QSCALE.
// ============================================================================
#define PAD   40
#define ATILE_B (128 * PAD * 2)              // 10240
#define BTILE_B (256 * PAD * 2)              // 20480
#define STAGE_BYTES (ATILE_B + BTILE_B)      // 30720
#define NSTAGE 4
#define GSMEM_TOTAL (NSTAGE * STAGE_BYTES)   // 122880

template<int ACT, int OUT, int SCALEQ>
__global__ __launch_bounds__(256, 1)
void mma_gemm(const __half* __restrict__ A,
              const __half* __restrict__ Bh,
              const float* __restrict__ bias,
              float* __restrict__ C,
              __half* __restrict__ Ch, __half* __restrict__ Cl,
              int M, int N, int K) {
    extern __shared__ char smem[];
    const uint32_t sbase = smem_u32(smem);
    const int tid  = threadIdx.x;
    const int bm   = blockIdx.y * 128;
    const int bn   = blockIdx.x * 256;

    const int wid  = tid >> 5;
    const int lane = tid & 31;
    const int wm   = (wid & 1) * 64;          // 2 warps in M
    const int wn   = (wid >> 1) * 64;         // 4 warps in N
    const int g    = lane >> 3;
    const int rig  = lane & 7;

    const __half* srcA = A  + (size_t)bm * K;
    const __half* srcB = Bh + (size_t)bn * K;

    float acc[4][8][4];
#pragma unroll
    for (int i = 0; i < 4; i++)
#pragma unroll
        for (int j = 0; j < 8; j++)
#pragma unroll
            for (int r = 0; r < 4; r++) acc[i][j][r] = 0.f;

    const int nt = K >> 5;
    const int lrow = tid >> 2;                 // 0..63
    const int lc4  = (tid & 3);

    // per stage: A (128 rows) + B (256 rows), each row 4 chunks of 16B
    auto load_stage = [&](int kt, int st) {
        const uint32_t sdst = sbase + st * STAGE_BYTES;
        const size_t koff = (size_t)kt * 32 + lc4 * 8;
        const uint32_t so = lc4 * 16;
#pragma unroll
        for (int p = 0; p < 2; p++) {          // A: rows lrow, lrow+64
            const int row = lrow + p * 64;
            cp16(sdst + row * PAD * 2 + so, srcA + (size_t)row * K + koff);
        }
#pragma unroll
        for (int p = 0; p < 4; p++) {          // B: rows lrow + 64p
            const int row = lrow + p * 64;
            cp16(sdst + ATILE_B + row * PAD * 2 + so, srcB + (size_t)row * K + koff);
        }
    };

    load_stage(0, 0); CP_COMMIT();
    load_stage(1, 1); CP_COMMIT();
    load_stage(2, 2); CP_COMMIT();

    const uint32_t aoff = ((wm + (g & 1) * 8 + rig) * PAD + (g >> 1) * 8) * 2;
    const uint32_t boff = ((wn + (g >> 1) * 8 + rig) * PAD + (g & 1) * 8) * 2;

    int stcur = 0;
    for (int kt = 0; kt < nt; kt++) {
        CP_WAIT(2);
        __syncthreads();
        if (kt + 3 < nt) {
            int stn = stcur + 3; if (stn >= NSTAGE) stn -= NSTAGE;
            load_stage(kt + 3, stn);
        }
        CP_COMMIT();

        const uint32_t st = sbase + stcur * STAGE_BYTES;
        const uint32_t sA = st;
        const uint32_t sB = st + ATILE_B;
        stcur++; if (stcur >= NSTAGE) stcur = 0;

#pragma unroll
        for (int ks = 0; ks < 2; ks++) {
            const uint32_t ko = ks * 32;
            uint32_t a0[4][4], b0[4][4];
#pragma unroll
            for (int jn = 0; jn < 4; jn++)
                ldsm4(b0[jn], sB + boff + ko + jn * 16 * PAD * 2);
#pragma unroll
            for (int i = 0; i < 4; i++)
                ldsm4(a0[i], sA + aoff + ko + i * 16 * PAD * 2);
#pragma unroll
            for (int i = 0; i < 4; i++)
#pragma unroll
                for (int j = 0; j < 8; j++)
                    mma16816(acc[i][j], a0[i],
                             b0[j >> 1][(j & 1) * 2],
                             b0[j >> 1][(j & 1) * 2 + 1]);
        }
        // no trailing sync: next iter's top sync orders compute(kt) reads
        // before loads into stage (kt+4)%4 == kt%4.
    }

    const int m_l = lane >> 2;
    const int n_l = (lane & 3) * 2;
#pragma unroll
    for (int j = 0; j < 8; j++) {
        const int n = bn + wn + j * 8 + n_l;
        const float2 b2 = *(const float2*)(bias + n);
        float qs = 1.f;
        if (SCALEQ) qs = ((n % 192) < 64) ? QSCALE_F : 1.f;
#pragma unroll
        for (int i = 0; i < 4; i++) {
            const int m = bm + wm + i * 16 + m_l;
            float v[4];
            v[0] = acc[i][j][0] + b2.x;
            v[1] = acc[i][j][1] + b2.y;
            v[2] = acc[i][j][2] + b2.x;
            v[3] = acc[i][j][3] + b2.y;
            if (ACT == 1) {
#pragma unroll
                for (int r = 0; r < 4; r++)
                    v[r] = 0.5f * v[r] * (1.0f + erff(v[r] * 0.70710678118654752f));
            }
            if (SCALEQ) {
#pragma unroll
                for (int r = 0; r < 4; r++) v[r] *= qs;
            }
            if (OUT == 0) {
                float2 o0; o0.x = v[0]; o0.y = v[1];
                float2 o1; o1.x = v[2]; o1.y = v[3];
                *(float2*)(C + (size_t)m * N + n)       = o0;
                *(float2*)(C + (size_t)(m + 8) * N + n) = o1;
            } else if (OUT == 1) {
                __half2 h0, l0, h1, l1;
                split2h(v[0], h0.x, l0.x); split2h(v[1], h0.y, l0.y);
                split2h(v[2], h1.x, l1.x); split2h(v[3], h1.y, l1.y);
                *(__half2*)(Ch + (size_t)m * N + n)       = h0;
                *(__half2*)(Cl + (size_t)m * N + n)       = l0;
                *(__half2*)(Ch + (size_t)(m + 8) * N + n) = h1;
                *(__half2*)(Cl + (size_t)(m + 8) * N + n) = l1;
            } else {
                *(__half2*)(Ch + (size_t)m * N + n)       = __floats2half2_rn(v[0], v[1]);
                *(__half2*)(Ch + (size_t)(m + 8) * N + n) = __floats2half2_rn(v[2], v[3]);
            }
        }
    }
}

// ============================================================================
// Tensor-core flash attention (unchanged from R10).
// ============================================================================
#define QP 72
#define QTILE_B (64 * QP * 2)
#define AQ_BYTES (2 * 2 * QTILE_B)
#define AST_BYTES (2 * QTILE_B)
#define ASMEM_TOTAL (AQ_BYTES + 2 * AST_BYTES)  // 73728

__global__ __launch_bounds__(256, 2)
void attn_tc(const __half* __restrict__ qkvh, const __half* __restrict__ qkvl,
             __half* __restrict__ ctxh) {
    extern __shared__ char smem[];
    const uint32_t sb  = smem_u32(smem);
    const uint32_t sQh = sb;
    const uint32_t sQl = sb + 2 * QTILE_B;
    const uint32_t sSt = sb + AQ_BYTES;

    const int q0 = blockIdx.x * 128;
    const int h  = blockIdx.y;
    const int b  = blockIdx.z;
    const int tid  = threadIdx.x;
    const int wid  = tid >> 5;
    const int lane = tid & 31;
    const int g    = lane >> 3;
    const int rig  = lane & 7;

    const size_t rowbase = (size_t)b * S_ * (3 * E_) + h * (3 * HD_);

    {
        const int r  = tid >> 1;
        const int cg = (tid & 1) * 4;
        const __half* sh = qkvh + rowbase + (size_t)(q0 + r) * (3 * E_) + cg * 8;
        const __half* sl = qkvl + rowbase + (size_t)(q0 + r) * (3 * E_) + cg * 8;
        const uint32_t d = r * QP * 2 + cg * 16;
#pragma unroll
        for (int j = 0; j < 4; j++) {
            cp16(sQh + d + j * 16, sh + j * 8);
            cp16(sQl + d + j * 16, sl + j * 8);
        }
    }

    auto load_kv = [&](int kt, int st) {
        const int r  = tid >> 2;
        const int cg = (tid & 3) * 2;
        const size_t grow = rowbase + (size_t)(kt * 64 + r) * (3 * E_);
        const uint32_t sd = sSt + st * AST_BYTES;
        const uint32_t d  = r * QP * 2 + cg * 16;
#pragma unroll
        for (int j = 0; j < 2; j++) {
            cp16(sd + 0 * QTILE_B + d + j * 16, qkvh + grow + HD_     + cg * 8 + j * 8);
            cp16(sd + 1 * QTILE_B + d + j * 16, qkvh + grow + 2 * HD_ + cg * 8 + j * 8);
        }
    };
    load_kv(0, 0);
    CP_COMMIT();

    float oacc[8][4];
#pragma unroll
    for (int j = 0; j < 8; j++)
#pragma unroll
        for (int r = 0; r < 4; r++) oacc[j][r] = 0.f;
    float m0 = -1e30f, m1 = -1e30f, l0 = 0.f, l1 = 0.f;

    const uint32_t aoff = ((wid * 16 + (g & 1) * 8 + rig) * QP + (g >> 1) * 8) * 2;
    const uint32_t koff = (((g >> 1) * 8 + rig) * QP + (g & 1) * 8) * 2;
    const uint32_t voff = (((g & 1) * 8 + rig) * QP + (g >> 1) * 8) * 2;

    const int NT = S_ / 64;
    for (int kt = 0; kt < NT; kt++) {
        CP_WAIT(0);
        __syncthreads();
        if (kt + 1 < NT) { load_kv(kt + 1, (kt + 1) & 1); CP_COMMIT(); }

        const uint32_t st  = sSt + (kt & 1) * AST_BYTES;
        const uint32_t sKh = st;
        const uint32_t sV  = st + QTILE_B;

        float sacc[8][4];
#pragma unroll
        for (int j = 0; j < 8; j++)
#pragma unroll
            for (int r = 0; r < 4; r++) sacc[j][r] = 0.f;

#pragma unroll
        for (int t = 0; t < 4; t++) {
            uint32_t qhf[4], qlf[4];
            ldsm4(qhf, sQh + aoff + t * 32);
            ldsm4(qlf, sQl + aoff + t * 32);
#pragma unroll
            for (int np = 0; np < 4; np++) {
                uint32_t kh[4];
                ldsm4(kh, sKh + koff + (np * 16 * QP + t * 16) * 2);
#pragma unroll
                for (int jj = 0; jj < 2; jj++) {
                    const int j = np * 2 + jj;
                    mma16816(sacc[j], qhf, kh[jj * 2], kh[jj * 2 + 1]);
                    mma16816(sacc[j], qlf, kh[jj * 2], kh[jj * 2 + 1]);
                }
            }
        }

        float mx0 = -1e30f, mx1 = -1e30f;
#pragma unroll
        for (int j = 0; j < 8; j++) {
            mx0 = fmaxf(mx0, fmaxf(sacc[j][0], sacc[j][1]));
            mx1 = fmaxf(mx1, fmaxf(sacc[j][2], sacc[j][3]));
        }
        mx0 = fmaxf(mx0, __shfl_xor_sync(0xffffffffu, mx0, 1));
        mx0 = fmaxf(mx0, __shfl_xor_sync(0xffffffffu, mx0, 2));
        mx1 = fmaxf(mx1, __shfl_xor_sync(0xffffffffu, mx1, 1));
        mx1 = fmaxf(mx1, __shfl_xor_sync(0xffffffffu, mx1, 2));

        const float m0n = fmaxf(m0, mx0);
        const float m1n = fmaxf(m1, mx1);
        const float al0 = exp2f(m0 - m0n);
        const float al1 = exp2f(m1 - m1n);
        m0 = m0n; m1 = m1n;

        uint32_t aPh[4][4], aPl[4][4];
        float ps0 = 0.f, ps1 = 0.f;
#pragma unroll
        for (int j = 0; j < 8; j++) {
            const float p0 = exp2f(sacc[j][0] - m0);
            const float p1 = exp2f(sacc[j][1] - m0);
            const float p2 = exp2f(sacc[j][2] - m1);
            const float p3 = exp2f(sacc[j][3] - m1);
            ps0 += p0 + p1; ps1 += p2 + p3;
            __half h0, h1, h2, h3, e0, e1, e2, e3;
            split2h(p0, h0, e0); split2h(p1, h1, e1);
            split2h(p2, h2, e2); split2h(p3, h3, e3);
            const int t = j >> 1, s = (j & 1) * 2;
            aPh[t][s]     = packh2(h0, h1);
            aPh[t][s + 1] = packh2(h2, h3);
            aPl[t][s]     = packh2(e0, e1);
            aPl[t][s + 1] = packh2(e2, e3);
        }
        ps0 += __shfl_xor_sync(0xffffffffu, ps0, 1);
        ps0 += __shfl_xor_sync(0xffffffffu, ps0, 2);
        ps1 += __shfl_xor_sync(0xffffffffu, ps1, 1);
        ps1 += __shfl_xor_sync(0xffffffffu, ps1, 2);
        l0 = l0 * al0 + ps0;
        l1 = l1 * al1 + ps1;

#pragma unroll
        for (int j = 0; j < 8; j++) {
            oacc[j][0] *= al0; oacc[j][1] *= al0;
            oacc[j][2] *= al1; oacc[j][3] *= al1;
        }

#pragma unroll
        for (int t = 0; t < 4; t++) {
#pragma unroll
            for (int dp = 0; dp < 4; dp++) {
                uint32_t vf[4];
                ldsm4t(vf, sV + voff + (t * 16 * QP + dp * 16) * 2);
#pragma unroll
                for (int jj = 0; jj < 2; jj++) {
                    const int jd = dp * 2 + jj;
                    mma16816(oacc[jd], aPh[t], vf[jj * 2], vf[jj * 2 + 1]);
                    mma16816(oacc[jd], aPl[t], vf[jj * 2], vf[jj * 2 + 1]);
                }
            }
        }
    }

    const float li0 = 1.0f / l0;
    const float li1 = 1.0f / l1;
    const int r0 = q0 + wid * 16 + (lane >> 2);
    const int dcol = (lane & 3) * 2;
#pragma unroll
    for (int j = 0; j < 8; j++) {
        const size_t o0 = ((size_t)b * S_ + r0) * E_ + h * HD_ + j * 8 + dcol;
        const size_t o1 = o0 + 8 * E_;
        *(__half2*)(ctxh + o0) = __floats2half2_rn(oacc[j][0] * li0, oacc[j][1] * li0);
        *(__half2*)(ctxh + o1) = __floats2half2_rn(oacc[j][2] * li1, oacc[j][3] * li1);
    }
}

// ============================================================================
// Fused residual-add + LayerNorm; optional fp16 (hi only) emission
// ============================================================================
template<int EMIT>
__global__ __launch_bounds__(256)
void add_ln_kernel(const float* __restrict__ x, const float* __restrict__ y,
                   const float* __restrict__ g, const float* __restrict__ beta,
                   float* __restrict__ out, __half* __restrict__ oh) {
    __shared__ float red1[8], red2[8];
    __shared__ float s_mean, s_rstd;
    const int row = blockIdx.x;
    const int tid = threadIdx.x;

    const float4 xv = ((const float4*)(x + (size_t)row * E_))[tid];
    const float4 yv = ((const float4*)(y + (size_t)row * E_))[tid];
    float v0 = xv.x + yv.x, v1 = xv.y + yv.y, v2 = xv.z + yv.z, v3 = xv.w + yv.w;

    float s  = v0 + v1 + v2 + v3;
    float ss = v0 * v0 + v1 * v1 + v2 * v2 + v3 * v3;
#pragma unroll
    for (int o = 16; o > 0; o >>= 1) {
        s  += __shfl_down_sync(0xffffffffu, s, o);
        ss += __shfl_down_sync(0xffffffffu, ss, o);
    }
    const int warp = tid >> 5, lane = tid & 31;
    if (lane == 0) { red1[warp] = s; red2[warp] = ss; }
    __syncthreads();
    if (tid == 0) {
        float ts = 0.f, tss = 0.f;
#pragma unroll
        for (int w = 0; w < 8; w++) { ts += red1[w]; tss += red2[w]; }
        float mean = ts * (1.0f / E_);
        float var  = tss * (1.0f / E_) - mean * mean;
        s_mean = mean;
        s_rstd = rsqrtf(var + 1e-5f);
    }
    __syncthreads();
    const float mean = s_mean, rstd = s_rstd;

    const float4 gv = ((const float4*)g)[tid];
    const float4 bv = ((const float4*)beta)[tid];
    float4 o;
    o.x = (v0 - mean) * rstd * gv.x + bv.x;
    o.y = (v1 - mean) * rstd * gv.y + bv.y;
    o.z = (v2 - mean) * rstd * gv.z + bv.z;
    o.w = (v3 - mean) * rstd * gv.w + bv.w;
    ((float4*)(out + (size_t)row * E_))[tid] = o;
    if (EMIT) {
        const size_t off = (size_t)row * E_ + tid * 4;
        *(__half2*)(oh + off)     = __floats2half2_rn(o.x, o.y);
        *(__half2*)(oh + off + 2) = __floats2half2_rn(o.z, o.w);
    }
}

// ============================================================================
// Launch
// ============================================================================
extern "C" void kernel_launch(void* const* d_in, const int* in_sizes, int n_in,
                              void* d_out, int out_size) {
    const float* x     = (const float*)d_in[0];
    const float* w_qkv = (const float*)d_in[1];
    const float* b_qkv = (const float*)d_in[2];
    const float* w_out = (const float*)d_in[3];
    const float* b_out = (const float*)d_in[4];
    const float* g1    = (const float*)d_in[5];
    const float* beta1 = (const float*)d_in[6];
    const float* g2    = (const float*)d_in[7];
    const float* beta2 = (const float*)d_in[8];
    const float* w1    = (const float*)d_in[9];
    const float* bf1   = (const float*)d_in[10];
    const float* w2    = (const float*)d_in[11];
    const float* bf2   = (const float*)d_in[12];
    float* out = (float*)d_out;

    float *tmp, *x1;
    cudaGetSymbolAddress((void**)&tmp,  g_tmp);
    cudaGetSymbolAddress((void**)&x1,   g_x1);

    __half *xh, *qkvh, *qkvl, *ctxh, *x1h, *hh;
    __half *wqkvh, *wouth, *w1h, *w2h;
    cudaGetSymbolAddress((void**)&xh, g_xh);
    cudaGetSymbolAddress((void**)&qkvh, g_qkvh);   cudaGetSymbolAddress((void**)&qkvl, g_qkvl);
    cudaGetSymbolAddress((void**)&ctxh, g_ctxh);
    cudaGetSymbolAddress((void**)&x1h, g_x1h);
    cudaGetSymbolAddress((void**)&hh, g_hh);
    cudaGetSymbolAddress((void**)&wqkvh, g_wqkvh);
    cudaGetSymbolAddress((void**)&wouth, g_wouth);
    cudaGetSymbolAddress((void**)&w1h, g_w1h);
    cudaGetSymbolAddress((void**)&w2h, g_w2h);

    cudaFuncSetAttribute(attn_tc, cudaFuncAttributeMaxDynamicSharedMemorySize, ASMEM_TOTAL);
    cudaFuncSetAttribute(mma_gemm<0,0,0>, cudaFuncAttributeMaxDynamicSharedMemorySize, GSMEM_TOTAL);
    cudaFuncSetAttribute(mma_gemm<0,1,1>, cudaFuncAttributeMaxDynamicSharedMemorySize, GSMEM_TOTAL);
    cudaFuncSetAttribute(mma_gemm<1,2,0>, cudaFuncAttributeMaxDynamicSharedMemorySize, GSMEM_TOTAL);

    dim3 thr(256);

    // 0: weights + x -> fp16
    conv_kernel<<<16384, thr>>>(w_qkv, w_out, w1, w2, x,
                                wqkvh, wouth, w1h, w2h, xh);

    // 1: qkv = x @ w_qkv^T + b_qkv -> fp16 hi/lo (Q pre-scaled)
    mma_gemm<0,1,1><<<dim3(3 * E_ / 256, M_ / 128), thr, GSMEM_TOTAL>>>(
        xh, wqkvh, b_qkv, nullptr, qkvh, qkvl, M_, 3 * E_, E_);

    // 2: flash attention -> ctx (fp16 hi)
    attn_tc<<<dim3(S_ / 128, H_, B_), thr, ASMEM_TOTAL>>>(qkvh, qkvl, ctxh);

    // 3: out-proj (fp32 out)
    mma_gemm<0,0,0><<<dim3(E_ / 256, M_ / 128), thr, GSMEM_TOTAL>>>(
        ctxh, wouth, b_out, tmp, nullptr, nullptr, M_, E_, E_);

    // 4: residual + LN -> x1 (+ fp16)
    add_ln_kernel<1><<<M_, thr>>>(x, tmp, g1, beta1, x1, x1h);

    // 5: h = gelu(x1 @ w1^T + bf1) -> fp16
    mma_gemm<1,2,0><<<dim3(FF_ / 256, M_ / 128), thr, GSMEM_TOTAL>>>(
        x1h, w1h, bf1, nullptr, hh, nullptr, M_, FF_, E_);

    // 6: ffn2 (fp32 out)
    mma_gemm<0,0,0><<<dim3(E_ / 256, M_ / 128), thr, GSMEM_TOTAL>>>(
        hh, w2h, bf2, tmp, nullptr, nullptr, M_, E_, FF_);

    // 7: residual + LN -> out
    add_ln_kernel<0><<<M_, thr>>>(x1, tmp, g2, beta2, out, nullptr);
}

// round 15
// speedup vs baseline: 1.1548x; 1.1548x over previous
#include <cuda_runtime.h>
#include <cuda_fp16.h>
#include <math.h>
#include <stdint.h>

// ---------------- problem constants ----------------
#define B_  2
#define S_  2048
#define E_  1024
#define H_  16
#define HD_ 64
#define FF_ 4096
#define M_  (B_ * S_)          // 4096 rows

// Q pre-scale: (1/sqrt(64)) * log2(e)
#define QSCALE_F 0.1803368801111244f

// ---------------- fp32 scratch ----------------
__device__ __align__(128) float g_tmp[(size_t)M_ * E_];
__device__ __align__(128) float g_x1 [(size_t)M_ * E_];

// ---------------- fp16 scratch ----------------
__device__ __align__(128) __half g_xh   [(size_t)M_ * E_];
__device__ __align__(128) __half g_qkvh [(size_t)M_ * 3 * E_], g_qkvl [(size_t)M_ * 3 * E_];
__device__ __align__(128) __half g_ctxh [(size_t)M_ * E_];
__device__ __align__(128) __half g_x1h  [(size_t)M_ * E_];
__device__ __align__(128) __half g_hh   [(size_t)M_ * FF_];
__device__ __align__(128) __half g_wqkvh[(size_t)3 * E_ * E_];
__device__ __align__(128) __half g_wouth[(size_t)E_ * E_];
__device__ __align__(128) __half g_w1h  [(size_t)FF_ * E_];
__device__ __align__(128) __half g_w2h  [(size_t)E_ * FF_];

// ============================================================================
// helpers
// ============================================================================
__device__ __forceinline__ uint32_t smem_u32(const void* p) {
    uint32_t a;
    asm("{ .reg .u64 t; cvta.to.shared.u64 t, %1; cvt.u32.u64 %0, t; }"
        : "=r"(a) : "l"(p));
    return a;
}

__device__ __forceinline__ void cp16(uint32_t dst, const void* src) {
    asm volatile("cp.async.cg.shared.global [%0], [%1], 16;"
                 :: "r"(dst), "l"(src) : "memory");
}
#define CP_COMMIT()  asm volatile("cp.async.commit_group;" ::: "memory")
#define CP_WAIT(N)   asm volatile("cp.async.wait_group %0;" :: "n"(N) : "memory")

__device__ __forceinline__ void ldsm4(uint32_t* r, uint32_t addr) {
    asm volatile("ldmatrix.sync.aligned.m8n8.x4.shared.b16 {%0,%1,%2,%3}, [%4];"
                 : "=r"(r[0]), "=r"(r[1]), "=r"(r[2]), "=r"(r[3]) : "r"(addr));
}
__device__ __forceinline__ void ldsm4t(uint32_t* r, uint32_t addr) {
    asm volatile("ldmatrix.sync.aligned.m8n8.x4.trans.shared.b16 {%0,%1,%2,%3}, [%4];"
                 : "=r"(r[0]), "=r"(r[1]), "=r"(r[2]), "=r"(r[3]) : "r"(addr));
}

__device__ __forceinline__ void mma16816(float d[4], const uint32_t a[4],
                                         uint32_t b0, uint32_t b1) {
    asm volatile(
        "mma.sync.aligned.m16n8k16.row.col.f32.f16.f16.f32 "
        "{%0,%1,%2,%3}, {%4,%5,%6,%7}, {%8,%9}, {%0,%1,%2,%3};"
        : "+f"(d[0]), "+f"(d[1]), "+f"(d[2]), "+f"(d[3])
        : "r"(a[0]), "r"(a[1]), "r"(a[2]), "r"(a[3]), "r"(b0), "r"(b1));
}

__device__ __forceinline__ void split2h(float v, __half& h, __half& l) {
    h = __float2half_rn(v);
    l = __float2half_rn(v - __half2float(h));
}
__device__ __forceinline__ uint32_t packh2f(float a, float b) {
    __half2 t = __floats2half2_rn(a, b);
    return *(uint32_t*)&t;
}

// ============================================================================
// Fused fp32 -> fp16 convert: 4 weights + x in one launch (16384 blocks).
// ============================================================================
__global__ __launch_bounds__(256)
void conv_kernel(const float* __restrict__ s0, const float* __restrict__ s1,
                 const float* __restrict__ s2, const float* __restrict__ s3,
                 const float* __restrict__ s4,
                 __half* __restrict__ d0, __half* __restrict__ d1,
                 __half* __restrict__ d2, __half* __restrict__ d3,
                 __half* __restrict__ d4) {
    const int b = blockIdx.x;
    const float* s; __half* d; int base;
    if      (b < 3072)  { s = s0; d = d0; base = b; }
    else if (b < 4096)  { s = s1; d = d1; base = b - 3072; }
    else if (b < 8192)  { s = s2; d = d2; base = b - 4096; }
    else if (b < 12288) { s = s3; d = d3; base = b - 8192; }
    else                { s = s4; d = d4; base = b - 12288; }
    const int i = base * 256 + threadIdx.x;
    float4 v = ((const float4*)s)[i];
    ((__half2*)d)[2 * i]     = __floats2half2_rn(v.x, v.y);
    ((__half2*)d)[2 * i + 1] = __floats2half2_rn(v.z, v.w);
}

// ============================================================================
// mma.sync HGEMM (R10 proven config): C = A[M,K] @ B[N,K]^T + bias.
// CTA 128x128, K-tile 32, 8 warps (2Mx4N), 4-stage cp.async, 2 CTAs/SM.
// ============================================================================
#define PAD   40
#define TILE_BYTES (128 * PAD * 2)           // 10240
#define STAGE_BYTES (2 * TILE_BYTES)         // A, B = 20480
#define NSTAGE 4
#define GSMEM_TOTAL (NSTAGE * STAGE_BYTES)   // 81920

template<int ACT, int OUT, int SCALEQ>
__global__ __launch_bounds__(256, 2)
void mma_gemm(const __half* __restrict__ A,
              const __half* __restrict__ Bh,
              const float* __restrict__ bias,
              float* __restrict__ C,
              __half* __restrict__ Ch, __half* __restrict__ Cl,
              int M, int N, int K) {
    extern __shared__ char smem[];
    const uint32_t sbase = smem_u32(smem);
    const int tid  = threadIdx.x;
    const int bm   = blockIdx.y * 128;
    const int bn   = blockIdx.x * 128;

    const int wid  = tid >> 5;
    const int lane = tid & 31;
    const int wm   = (wid & 1) * 64;
    const int wn   = (wid >> 1) * 32;
    const int g    = lane >> 3;
    const int rig  = lane & 7;

    const __half* srcA = A  + (size_t)bm * K;
    const __half* srcB = Bh + (size_t)bn * K;

    float acc[4][4][4];
#pragma unroll
    for (int i = 0; i < 4; i++)
#pragma unroll
        for (int j = 0; j < 4; j++)
#pragma unroll
            for (int r = 0; r < 4; r++) acc[i][j][r] = 0.f;

    const int nt = K >> 5;
    const int lrow = tid >> 2;
    const int lc4  = (tid & 3);

    auto load_stage = [&](int kt, int st) {
        const uint32_t sdst = sbase + st * STAGE_BYTES;
        const size_t koff = (size_t)kt * 32 + lc4 * 8;
        const uint32_t so = lc4 * 16;
#pragma unroll
        for (int half_ = 0; half_ < 2; half_++) {
            const int row = lrow + half_ * 64;
            const uint32_t rowo = row * PAD * 2 + so;
            const size_t gof = (size_t)row * K + koff;
            cp16(sdst + 0 * TILE_BYTES + rowo, srcA + gof);
            cp16(sdst + 1 * TILE_BYTES + rowo, srcB + gof);
        }
    };

    load_stage(0, 0); CP_COMMIT();
    load_stage(1, 1); CP_COMMIT();
    load_stage(2, 2); CP_COMMIT();

    const uint32_t aoff = ((wm + (g & 1) * 8 + rig) * PAD + (g >> 1) * 8) * 2;
    const uint32_t boff = ((wn + (g >> 1) * 8 + rig) * PAD + (g & 1) * 8) * 2;

    int stcur = 0;
    for (int kt = 0; kt < nt; kt++) {
        CP_WAIT(2);
        __syncthreads();
        if (kt + 3 < nt) {
            int stn = stcur + 3; if (stn >= NSTAGE) stn -= NSTAGE;
            load_stage(kt + 3, stn);
        }
        CP_COMMIT();

        const uint32_t st = sbase + stcur * STAGE_BYTES;
        const uint32_t sA = st;
        const uint32_t sB = st + TILE_BYTES;
        stcur++; if (stcur >= NSTAGE) stcur = 0;

#pragma unroll
        for (int ks = 0; ks < 2; ks++) {
            const uint32_t ko = ks * 32;
            uint32_t a0[4][4], b0[2][4];
#pragma unroll
            for (int j2 = 0; j2 < 2; j2++) ldsm4(b0[j2], sB + boff + ko + j2 * 16 * PAD * 2);
#pragma unroll
            for (int i = 0; i < 4; i++) ldsm4(a0[i], sA + aoff + ko + i * 16 * PAD * 2);
#pragma unroll
            for (int i = 0; i < 4; i++)
#pragma unroll
                for (int j = 0; j < 4; j++)
                    mma16816(acc[i][j], a0[i], b0[j >> 1][(j & 1) * 2], b0[j >> 1][(j & 1) * 2 + 1]);
        }
    }

    const int m_l = lane >> 2;
    const int n_l = (lane & 3) * 2;
#pragma unroll
    for (int j = 0; j < 4; j++) {
        const int n = bn + wn + j * 8 + n_l;
        const float2 b2 = *(const float2*)(bias + n);
        float qs = 1.f;
        if (SCALEQ) qs = ((n % 192) < 64) ? QSCALE_F : 1.f;
#pragma unroll
        for (int i = 0; i < 4; i++) {
            const int m = bm + wm + i * 16 + m_l;
            float v[4];
            v[0] = acc[i][j][0] + b2.x;
            v[1] = acc[i][j][1] + b2.y;
            v[2] = acc[i][j][2] + b2.x;
            v[3] = acc[i][j][3] + b2.y;
            if (ACT == 1) {
#pragma unroll
                for (int r = 0; r < 4; r++)
                    v[r] = 0.5f * v[r] * (1.0f + erff(v[r] * 0.70710678118654752f));
            }
            if (SCALEQ) {
#pragma unroll
                for (int r = 0; r < 4; r++) v[r] *= qs;
            }
            if (OUT == 0) {
                float2 o0; o0.x = v[0]; o0.y = v[1];
                float2 o1; o1.x = v[2]; o1.y = v[3];
                *(float2*)(C + (size_t)m * N + n)       = o0;
                *(float2*)(C + (size_t)(m + 8) * N + n) = o1;
            } else if (OUT == 1) {
                __half2 h0, l0, h1, l1;
                split2h(v[0], h0.x, l0.x); split2h(v[1], h0.y, l0.y);
                split2h(v[2], h1.x, l1.x); split2h(v[3], h1.y, l1.y);
                *(__half2*)(Ch + (size_t)m * N + n)       = h0;
                *(__half2*)(Cl + (size_t)m * N + n)       = l0;
                *(__half2*)(Ch + (size_t)(m + 8) * N + n) = h1;
                *(__half2*)(Cl + (size_t)(m + 8) * N + n) = l1;
            } else {
                *(__half2*)(Ch + (size_t)m * N + n)       = __floats2half2_rn(v[0], v[1]);
                *(__half2*)(Ch + (size_t)(m + 8) * N + n) = __floats2half2_rn(v[2], v[3]);
            }
        }
    }
}

// ============================================================================
// Tensor-core flash attention.
// S = (Qh+Ql) Kh^T (2-term);  PV = Ph V (single term; P>=0 so fp16
// carries full relative precision).
// ============================================================================
#define QP 72
#define QTILE_B (64 * QP * 2)
#define AQ_BYTES (2 * 2 * QTILE_B)
#define AST_BYTES (2 * QTILE_B)
#define ASMEM_TOTAL (AQ_BYTES + 2 * AST_BYTES)  // 73728

__global__ __launch_bounds__(256, 2)
void attn_tc(const __half* __restrict__ qkvh, const __half* __restrict__ qkvl,
             __half* __restrict__ ctxh) {
    extern __shared__ char smem[];
    const uint32_t sb  = smem_u32(smem);
    const uint32_t sQh = sb;
    const uint32_t sQl = sb + 2 * QTILE_B;
    const uint32_t sSt = sb + AQ_BYTES;

    const int q0 = blockIdx.x * 128;
    const int h  = blockIdx.y;
    const int b  = blockIdx.z;
    const int tid  = threadIdx.x;
    const int wid  = tid >> 5;
    const int lane = tid & 31;
    const int g    = lane >> 3;
    const int rig  = lane & 7;

    const size_t rowbase = (size_t)b * S_ * (3 * E_) + h * (3 * HD_);

    {
        const int r  = tid >> 1;
        const int cg = (tid & 1) * 4;
        const __half* sh = qkvh + rowbase + (size_t)(q0 + r) * (3 * E_) + cg * 8;
        const __half* sl = qkvl + rowbase + (size_t)(q0 + r) * (3 * E_) + cg * 8;
        const uint32_t d = r * QP * 2 + cg * 16;
#pragma unroll
        for (int j = 0; j < 4; j++) {
            cp16(sQh + d + j * 16, sh + j * 8);
            cp16(sQl + d + j * 16, sl + j * 8);
        }
    }

    auto load_kv = [&](int kt, int st) {
        const int r  = tid >> 2;
        const int cg = (tid & 3) * 2;
        const size_t grow = rowbase + (size_t)(kt * 64 + r) * (3 * E_);
        const uint32_t sd = sSt + st * AST_BYTES;
        const uint32_t d  = r * QP * 2 + cg * 16;
#pragma unroll
        for (int j = 0; j < 2; j++) {
            cp16(sd + 0 * QTILE_B + d + j * 16, qkvh + grow + HD_     + cg * 8 + j * 8);
            cp16(sd + 1 * QTILE_B + d + j * 16, qkvh + grow + 2 * HD_ + cg * 8 + j * 8);
        }
    };
    load_kv(0, 0);
    CP_COMMIT();

    float oacc[8][4];
#pragma unroll
    for (int j = 0; j < 8; j++)
#pragma unroll
        for (int r = 0; r < 4; r++) oacc[j][r] = 0.f;
    float m0 = -1e30f, m1 = -1e30f, l0 = 0.f, l1 = 0.f;

    const uint32_t aoff = ((wid * 16 + (g & 1) * 8 + rig) * QP + (g >> 1) * 8) * 2;
    const uint32_t koff = (((g >> 1) * 8 + rig) * QP + (g & 1) * 8) * 2;
    const uint32_t voff = (((g & 1) * 8 + rig) * QP + (g >> 1) * 8) * 2;

    const int NT = S_ / 64;
    for (int kt = 0; kt < NT; kt++) {
        CP_WAIT(0);
        __syncthreads();
        if (kt + 1 < NT) { load_kv(kt + 1, (kt + 1) & 1); CP_COMMIT(); }

        const uint32_t st  = sSt + (kt & 1) * AST_BYTES;
        const uint32_t sKh = st;
        const uint32_t sV  = st + QTILE_B;

        // S = (Qh+Ql) Kh^T
        float sacc[8][4];
#pragma unroll
        for (int j = 0; j < 8; j++)
#pragma unroll
            for (int r = 0; r < 4; r++) sacc[j][r] = 0.f;

#pragma unroll
        for (int t = 0; t < 4; t++) {
            uint32_t qhf[4], qlf[4];
            ldsm4(qhf, sQh + aoff + t * 32);
            ldsm4(qlf, sQl + aoff + t * 32);
#pragma unroll
            for (int np = 0; np < 4; np++) {
                uint32_t kh[4];
                ldsm4(kh, sKh + koff + (np * 16 * QP + t * 16) * 2);
#pragma unroll
                for (int jj = 0; jj < 2; jj++) {
                    const int j = np * 2 + jj;
                    mma16816(sacc[j], qhf, kh[jj * 2], kh[jj * 2 + 1]);
                    mma16816(sacc[j], qlf, kh[jj * 2], kh[jj * 2 + 1]);
                }
            }
        }

        // online softmax (log2 domain)
        float mx0 = -1e30f, mx1 = -1e30f;
#pragma unroll
        for (int j = 0; j < 8; j++) {
            mx0 = fmaxf(mx0, fmaxf(sacc[j][0], sacc[j][1]));
            mx1 = fmaxf(mx1, fmaxf(sacc[j][2], sacc[j][3]));
        }
        mx0 = fmaxf(mx0, __shfl_xor_sync(0xffffffffu, mx0, 1));
        mx0 = fmaxf(mx0, __shfl_xor_sync(0xffffffffu, mx0, 2));
        mx1 = fmaxf(mx1, __shfl_xor_sync(0xffffffffu, mx1, 1));
        mx1 = fmaxf(mx1, __shfl_xor_sync(0xffffffffu, mx1, 2));

        const float m0n = fmaxf(m0, mx0);
        const float m1n = fmaxf(m1, mx1);
        const float al0 = exp2f(m0 - m0n);
        const float al1 = exp2f(m1 - m1n);
        m0 = m0n; m1 = m1n;

        uint32_t aPh[4][4];
        float ps0 = 0.f, ps1 = 0.f;
#pragma unroll
        for (int j = 0; j < 8; j++) {
            const float p0 = exp2f(sacc[j][0] - m0);
            const float p1 = exp2f(sacc[j][1] - m0);
            const float p2 = exp2f(sacc[j][2] - m1);
            const float p3 = exp2f(sacc[j][3] - m1);
            ps0 += p0 + p1; ps1 += p2 + p3;
            const int t = j >> 1, s = (j & 1) * 2;
            aPh[t][s]     = packh2f(p0, p1);
            aPh[t][s + 1] = packh2f(p2, p3);
        }
        ps0 += __shfl_xor_sync(0xffffffffu, ps0, 1);
        ps0 += __shfl_xor_sync(0xffffffffu, ps0, 2);
        ps1 += __shfl_xor_sync(0xffffffffu, ps1, 1);
        ps1 += __shfl_xor_sync(0xffffffffu, ps1, 2);
        l0 = l0 * al0 + ps0;
        l1 = l1 * al1 + ps1;

#pragma unroll
        for (int j = 0; j < 8; j++) {
            oacc[j][0] *= al0; oacc[j][1] *= al0;
            oacc[j][2] *= al1; oacc[j][3] *= al1;
        }

        // O += Ph V   (single term)
#pragma unroll
        for (int t = 0; t < 4; t++) {
#pragma unroll
            for (int dp = 0; dp < 4; dp++) {
                uint32_t vf[4];
                ldsm4t(vf, sV + voff + (t * 16 * QP + dp * 16) * 2);
#pragma unroll
                for (int jj = 0; jj < 2; jj++) {
                    const int jd = dp * 2 + jj;
                    mma16816(oacc[jd], aPh[t], vf[jj * 2], vf[jj * 2 + 1]);
                }
            }
        }
    }

    const float li0 = 1.0f / l0;
    const float li1 = 1.0f / l1;
    const int r0 = q0 + wid * 16 + (lane >> 2);
    const int dcol = (lane & 3) * 2;
#pragma unroll
    for (int j = 0; j < 8; j++) {
        const size_t o0 = ((size_t)b * S_ + r0) * E_ + h * HD_ + j * 8 + dcol;
        const size_t o1 = o0 + 8 * E_;
        *(__half2*)(ctxh + o0) = __floats2half2_rn(oacc[j][0] * li0, oacc[j][1] * li0);
        *(__half2*)(ctxh + o1) = __floats2half2_rn(oacc[j][2] * li1, oacc[j][3] * li1);
    }
}

// ============================================================================
// Fused residual-add + LayerNorm; optional fp16 (hi only) emission
// ============================================================================
template<int EMIT>
__global__ __launch_bounds__(256)
void add_ln_kernel(const float* __restrict__ x, const float* __restrict__ y,
                   const float* __restrict__ g, const float* __restrict__ beta,
                   float* __restrict__ out, __half* __restrict__ oh) {
    __shared__ float red1[8], red2[8];
    __shared__ float s_mean, s_rstd;
    const int row = blockIdx.x;
    const int tid = threadIdx.x;

    const float4 xv = ((const float4*)(x + (size_t)row * E_))[tid];
    const float4 yv = ((const float4*)(y + (size_t)row * E_))[tid];
    float v0 = xv.x + yv.x, v1 = xv.y + yv.y, v2 = xv.z + yv.z, v3 = xv.w + yv.w;

    float s  = v0 + v1 + v2 + v3;
    float ss = v0 * v0 + v1 * v1 + v2 * v2 + v3 * v3;
#pragma unroll
    for (int o = 16; o > 0; o >>= 1) {
        s  += __shfl_down_sync(0xffffffffu, s, o);
        ss += __shfl_down_sync(0xffffffffu, ss, o);
    }
    const int warp = tid >> 5, lane = tid & 31;
    if (lane == 0) { red1[warp] = s; red2[warp] = ss; }
    __syncthreads();
    if (tid == 0) {
        float ts = 0.f, tss = 0.f;
#pragma unroll
        for (int w = 0; w < 8; w++) { ts += red1[w]; tss += red2[w]; }
        float mean = ts * (1.0f / E_);
        float var  = tss * (1.0f / E_) - mean * mean;
        s_mean = mean;
        s_rstd = rsqrtf(var + 1e-5f);
    }
    __syncthreads();
    const float mean = s_mean, rstd = s_rstd;

    const float4 gv = ((const float4*)g)[tid];
    const float4 bv = ((const float4*)beta)[tid];
    float4 o;
    o.x = (v0 - mean) * rstd * gv.x + bv.x;
    o.y = (v1 - mean) * rstd * gv.y + bv.y;
    o.z = (v2 - mean) * rstd * gv.z + bv.z;
    o.w = (v3 - mean) * rstd * gv.w + bv.w;
    ((float4*)(out + (size_t)row * E_))[tid] = o;
    if (EMIT) {
        const size_t off = (size_t)row * E_ + tid * 4;
        *(__half2*)(oh + off)     = __floats2half2_rn(o.x, o.y);
        *(__half2*)(oh + off + 2) = __floats2half2_rn(o.z, o.w);
    }
}

// ============================================================================
// Launch
// ============================================================================
extern "C" void kernel_launch(void* const* d_in, const int* in_sizes, int n_in,
                              void* d_out, int out_size) {
    const float* x     = (const float*)d_in[0];
    const float* w_qkv = (const float*)d_in[1];
    const float* b_qkv = (const float*)d_in[2];
    const float* w_out = (const float*)d_in[3];
    const float* b_out = (const float*)d_in[4];
    const float* g1    = (const float*)d_in[5];
    const float* beta1 = (const float*)d_in[6];
    const float* g2    = (const float*)d_in[7];
    const float* beta2 = (const float*)d_in[8];
    const float* w1    = (const float*)d_in[9];
    const float* bf1   = (const float*)d_in[10];
    const float* w2    = (const float*)d_in[11];
    const float* bf2   = (const float*)d_in[12];
    float* out = (float*)d_out;

    float *tmp, *x1;
    cudaGetSymbolAddress((void**)&tmp,  g_tmp);
    cudaGetSymbolAddress((void**)&x1,   g_x1);

    __half *xh, *qkvh, *qkvl, *ctxh, *x1h, *hh;
    __half *wqkvh, *wouth, *w1h, *w2h;
    cudaGetSymbolAddress((void**)&xh, g_xh);
    cudaGetSymbolAddress((void**)&qkvh, g_qkvh);   cudaGetSymbolAddress((void**)&qkvl, g_qkvl);
    cudaGetSymbolAddress((void**)&ctxh, g_ctxh);
    cudaGetSymbolAddress((void**)&x1h, g_x1h);
    cudaGetSymbolAddress((void**)&hh, g_hh);
    cudaGetSymbolAddress((void**)&wqkvh, g_wqkvh);
    cudaGetSymbolAddress((void**)&wouth, g_wouth);
    cudaGetSymbolAddress((void**)&w1h, g_w1h);
    cudaGetSymbolAddress((void**)&w2h, g_w2h);

    cudaFuncSetAttribute(attn_tc, cudaFuncAttributeMaxDynamicSharedMemorySize, ASMEM_TOTAL);
    cudaFuncSetAttribute(mma_gemm<0,0,0>, cudaFuncAttributeMaxDynamicSharedMemorySize, GSMEM_TOTAL);
    cudaFuncSetAttribute(mma_gemm<0,1,1>, cudaFuncAttributeMaxDynamicSharedMemorySize, GSMEM_TOTAL);
    cudaFuncSetAttribute(mma_gemm<1,2,0>, cudaFuncAttributeMaxDynamicSharedMemorySize, GSMEM_TOTAL);

    dim3 thr(256);

    // 0: weights + x -> fp16
    conv_kernel<<<16384, thr>>>(w_qkv, w_out, w1, w2, x,
                                wqkvh, wouth, w1h, w2h, xh);

    // 1: qkv = x @ w_qkv^T + b_qkv -> fp16 hi/lo (Q pre-scaled)
    mma_gemm<0,1,1><<<dim3(3 * E_ / 128, M_ / 128), thr, GSMEM_TOTAL>>>(
        xh, wqkvh, b_qkv, nullptr, qkvh, qkvl, M_, 3 * E_, E_);

    // 2: flash attention -> ctx (fp16 hi)
    attn_tc<<<dim3(S_ / 128, H_, B_), thr, ASMEM_TOTAL>>>(qkvh, qkvl, ctxh);

    // 3: out-proj (fp32 out)
    mma_gemm<0,0,0><<<dim3(E_ / 128, M_ / 128), thr, GSMEM_TOTAL>>>(
        ctxh, wouth, b_out, tmp, nullptr, nullptr, M_, E_, E_);

    // 4: residual + LN -> x1 (+ fp16)
    add_ln_kernel<1><<<M_, thr>>>(x, tmp, g1, beta1, x1, x1h);

    // 5: h = gelu(x1 @ w1^T + bf1) -> fp16
    mma_gemm<1,2,0><<<dim3(FF_ / 128, M_ / 128), thr, GSMEM_TOTAL>>>(
        x1h, w1h, bf1, nullptr, hh, nullptr, M_, FF_, E_);

    // 6: ffn2 (fp32 out)
    mma_gemm<0,0,0><<<dim3(E_ / 128, M_ / 128), thr, GSMEM_TOTAL>>>(
        hh, w2h, bf2, tmp, nullptr, nullptr, M_, E_, FF_);

    // 7: residual + LN -> out
    add_ln_kernel<0><<<M_, thr>>>(x1, tmp, g2, beta2, out, nullptr);
}

// round 16
// speedup vs baseline: 1.2503x; 1.0826x over previous
#include <cuda_runtime.h>
#include <cuda_fp16.h>
#include <math.h>
#include <stdint.h>

// ---------------- problem constants ----------------
#define B_  2
#define S_  2048
#define E_  1024
#define H_  16
#define HD_ 64
#define FF_ 4096
#define M_  (B_ * S_)          // 4096 rows

// Q pre-scale: (1/sqrt(64)) * log2(e)
#define QSCALE_F 0.1803368801111244f

// ---------------- fp32 scratch ----------------
__device__ __align__(128) float g_tmp[(size_t)M_ * E_];
__device__ __align__(128) float g_x1 [(size_t)M_ * E_];

// ---------------- fp16 scratch ----------------
__device__ __align__(128) __half g_xh   [(size_t)M_ * E_];
__device__ __align__(128) __half g_qkvh [(size_t)M_ * 3 * E_];
__device__ __align__(128) __half g_ctxh [(size_t)M_ * E_];
__device__ __align__(128) __half g_x1h  [(size_t)M_ * E_];
__device__ __align__(128) __half g_hh   [(size_t)M_ * FF_];
__device__ __align__(128) __half g_wqkvh[(size_t)3 * E_ * E_];
__device__ __align__(128) __half g_wouth[(size_t)E_ * E_];
__device__ __align__(128) __half g_w1h  [(size_t)FF_ * E_];
__device__ __align__(128) __half g_w2h  [(size_t)E_ * FF_];

// ============================================================================
// helpers
// ============================================================================
__device__ __forceinline__ uint32_t smem_u32(const void* p) {
    uint32_t a;
    asm("{ .reg .u64 t; cvta.to.shared.u64 t, %1; cvt.u32.u64 %0, t; }"
        : "=r"(a) : "l"(p));
    return a;
}

__device__ __forceinline__ void cp16(uint32_t dst, const void* src) {
    asm volatile("cp.async.cg.shared.global [%0], [%1], 16;"
                 :: "r"(dst), "l"(src) : "memory");
}
#define CP_COMMIT()  asm volatile("cp.async.commit_group;" ::: "memory")
#define CP_WAIT(N)   asm volatile("cp.async.wait_group %0;" :: "n"(N) : "memory")

__device__ __forceinline__ void ldsm4(uint32_t* r, uint32_t addr) {
    asm volatile("ldmatrix.sync.aligned.m8n8.x4.shared.b16 {%0,%1,%2,%3}, [%4];"
                 : "=r"(r[0]), "=r"(r[1]), "=r"(r[2]), "=r"(r[3]) : "r"(addr));
}
__device__ __forceinline__ void ldsm4t(uint32_t* r, uint32_t addr) {
    asm volatile("ldmatrix.sync.aligned.m8n8.x4.trans.shared.b16 {%0,%1,%2,%3}, [%4];"
                 : "=r"(r[0]), "=r"(r[1]), "=r"(r[2]), "=r"(r[3]) : "r"(addr));
}

__device__ __forceinline__ void mma16816(float d[4], const uint32_t a[4],
                                         uint32_t b0, uint32_t b1) {
    asm volatile(
        "mma.sync.aligned.m16n8k16.row.col.f32.f16.f16.f32 "
        "{%0,%1,%2,%3}, {%4,%5,%6,%7}, {%8,%9}, {%0,%1,%2,%3};"
        : "+f"(d[0]), "+f"(d[1]), "+f"(d[2]), "+f"(d[3])
        : "r"(a[0]), "r"(a[1]), "r"(a[2]), "r"(a[3]), "r"(b0), "r"(b1));
}

__device__ __forceinline__ void split2h(float v, __half& h, __half& l) {
    h = __float2half_rn(v);
    l = __float2half_rn(v - __half2float(h));
}
__device__ __forceinline__ uint32_t packh2f(float a, float b) {
    __half2 t = __floats2half2_rn(a, b);
    return *(uint32_t*)&t;
}

// ============================================================================
// Fused fp32 -> fp16 convert: 4 weights + x in one launch (16384 blocks).
// ============================================================================
__global__ __launch_bounds__(256)
void conv_kernel(const float* __restrict__ s0, const float* __restrict__ s1,
                 const float* __restrict__ s2, const float* __restrict__ s3,
                 const float* __restrict__ s4,
                 __half* __restrict__ d0, __half* __restrict__ d1,
                 __half* __restrict__ d2, __half* __restrict__ d3,
                 __half* __restrict__ d4) {
    const int b = blockIdx.x;
    const float* s; __half* d; int base;
    if      (b < 3072)  { s = s0; d = d0; base = b; }
    else if (b < 4096)  { s = s1; d = d1; base = b - 3072; }
    else if (b < 8192)  { s = s2; d = d2; base = b - 4096; }
    else if (b < 12288) { s = s3; d = d3; base = b - 8192; }
    else                { s = s4; d = d4; base = b - 12288; }
    const int i = base * 256 + threadIdx.x;
    float4 v = ((const float4*)s)[i];
    ((__half2*)d)[2 * i]     = __floats2half2_rn(v.x, v.y);
    ((__half2*)d)[2 * i + 1] = __floats2half2_rn(v.z, v.w);
}

// ============================================================================
// mma.sync HGEMM (R10 proven config): C = A[M,K] @ B[N,K]^T + bias.
// CTA 128x128, K-tile 32, 8 warps (2Mx4N), 4-stage cp.async, 2 CTAs/SM.
// ACT: 0/1 GELU.  OUT: 0 fp32, 2 fp16 (hi only).  SCALEQ: Q-col scaling.
// ============================================================================
#define PAD   40
#define TILE_BYTES (128 * PAD * 2)           // 10240
#define STAGE_BYTES (2 * TILE_BYTES)         // A, B = 20480
#define NSTAGE 4
#define GSMEM_TOTAL (NSTAGE * STAGE_BYTES)   // 81920

template<int ACT, int OUT, int SCALEQ>
__global__ __launch_bounds__(256, 2)
void mma_gemm(const __half* __restrict__ A,
              const __half* __restrict__ Bh,
              const float* __restrict__ bias,
              float* __restrict__ C,
              __half* __restrict__ Ch,
              int M, int N, int K) {
    extern __shared__ char smem[];
    const uint32_t sbase = smem_u32(smem);
    const int tid  = threadIdx.x;
    const int bm   = blockIdx.y * 128;
    const int bn   = blockIdx.x * 128;

    const int wid  = tid >> 5;
    const int lane = tid & 31;
    const int wm   = (wid & 1) * 64;
    const int wn   = (wid >> 1) * 32;
    const int g    = lane >> 3;
    const int rig  = lane & 7;

    const __half* srcA = A  + (size_t)bm * K;
    const __half* srcB = Bh + (size_t)bn * K;

    float acc[4][4][4];
#pragma unroll
    for (int i = 0; i < 4; i++)
#pragma unroll
        for (int j = 0; j < 4; j++)
#pragma unroll
            for (int r = 0; r < 4; r++) acc[i][j][r] = 0.f;

    const int nt = K >> 5;
    const int lrow = tid >> 2;
    const int lc4  = (tid & 3);

    auto load_stage = [&](int kt, int st) {
        const uint32_t sdst = sbase + st * STAGE_BYTES;
        const size_t koff = (size_t)kt * 32 + lc4 * 8;
        const uint32_t so = lc4 * 16;
#pragma unroll
        for (int half_ = 0; half_ < 2; half_++) {
            const int row = lrow + half_ * 64;
            const uint32_t rowo = row * PAD * 2 + so;
            const size_t gof = (size_t)row * K + koff;
            cp16(sdst + 0 * TILE_BYTES + rowo, srcA + gof);
            cp16(sdst + 1 * TILE_BYTES + rowo, srcB + gof);
        }
    };

    load_stage(0, 0); CP_COMMIT();
    load_stage(1, 1); CP_COMMIT();
    load_stage(2, 2); CP_COMMIT();

    const uint32_t aoff = ((wm + (g & 1) * 8 + rig) * PAD + (g >> 1) * 8) * 2;
    const uint32_t boff = ((wn + (g >> 1) * 8 + rig) * PAD + (g & 1) * 8) * 2;

    int stcur = 0;
    for (int kt = 0; kt < nt; kt++) {
        CP_WAIT(2);
        __syncthreads();
        if (kt + 3 < nt) {
            int stn = stcur + 3; if (stn >= NSTAGE) stn -= NSTAGE;
            load_stage(kt + 3, stn);
        }
        CP_COMMIT();

        const uint32_t st = sbase + stcur * STAGE_BYTES;
        const uint32_t sA = st;
        const uint32_t sB = st + TILE_BYTES;
        stcur++; if (stcur >= NSTAGE) stcur = 0;

#pragma unroll
        for (int ks = 0; ks < 2; ks++) {
            const uint32_t ko = ks * 32;
            uint32_t a0[4][4], b0[2][4];
#pragma unroll
            for (int j2 = 0; j2 < 2; j2++) ldsm4(b0[j2], sB + boff + ko + j2 * 16 * PAD * 2);
#pragma unroll
            for (int i = 0; i < 4; i++) ldsm4(a0[i], sA + aoff + ko + i * 16 * PAD * 2);
#pragma unroll
            for (int i = 0; i < 4; i++)
#pragma unroll
                for (int j = 0; j < 4; j++)
                    mma16816(acc[i][j], a0[i], b0[j >> 1][(j & 1) * 2], b0[j >> 1][(j & 1) * 2 + 1]);
        }
    }

    const int m_l = lane >> 2;
    const int n_l = (lane & 3) * 2;
#pragma unroll
    for (int j = 0; j < 4; j++) {
        const int n = bn + wn + j * 8 + n_l;
        const float2 b2 = *(const float2*)(bias + n);
        float qs = 1.f;
        if (SCALEQ) qs = ((n % 192) < 64) ? QSCALE_F : 1.f;
#pragma unroll
        for (int i = 0; i < 4; i++) {
            const int m = bm + wm + i * 16 + m_l;
            float v[4];
            v[0] = acc[i][j][0] + b2.x;
            v[1] = acc[i][j][1] + b2.y;
            v[2] = acc[i][j][2] + b2.x;
            v[3] = acc[i][j][3] + b2.y;
            if (ACT == 1) {
#pragma unroll
                for (int r = 0; r < 4; r++)
                    v[r] = 0.5f * v[r] * (1.0f + erff(v[r] * 0.70710678118654752f));
            }
            if (SCALEQ) {
#pragma unroll
                for (int r = 0; r < 4; r++) v[r] *= qs;
            }
            if (OUT == 0) {
                float2 o0; o0.x = v[0]; o0.y = v[1];
                float2 o1; o1.x = v[2]; o1.y = v[3];
                *(float2*)(C + (size_t)m * N + n)       = o0;
                *(float2*)(C + (size_t)(m + 8) * N + n) = o1;
            } else {
                *(__half2*)(Ch + (size_t)m * N + n)       = __floats2half2_rn(v[0], v[1]);
                *(__half2*)(Ch + (size_t)(m + 8) * N + n) = __floats2half2_rn(v[2], v[3]);
            }
        }
    }
}

// ============================================================================
// Tensor-core flash attention.
// S = Qh Kh^T (single term — fp16 weights set the error floor; the Ql
// term was measured to contribute nothing: rel_err identical with/without
// the symmetric Kl term in R8).  PV = Ph V (single term).
// ============================================================================
#define QP 72
#define QTILE_B (64 * QP * 2)
#define AQ_BYTES (2 * QTILE_B)                  // Q hi, 128 rows = 18432
#define AST_BYTES (2 * QTILE_B)
#define ASMEM_TOTAL (AQ_BYTES + 2 * AST_BYTES)  // 55296

__global__ __launch_bounds__(256, 2)
void attn_tc(const __half* __restrict__ qkvh, __half* __restrict__ ctxh) {
    extern __shared__ char smem[];
    const uint32_t sb  = smem_u32(smem);
    const uint32_t sQh = sb;
    const uint32_t sSt = sb + AQ_BYTES;

    const int q0 = blockIdx.x * 128;
    const int h  = blockIdx.y;
    const int b  = blockIdx.z;
    const int tid  = threadIdx.x;
    const int wid  = tid >> 5;
    const int lane = tid & 31;
    const int g    = lane >> 3;
    const int rig  = lane & 7;

    const size_t rowbase = (size_t)b * S_ * (3 * E_) + h * (3 * HD_);

    // Q hi: 128 rows x 64 halfs
    {
        const int r  = tid >> 1;
        const int cg = (tid & 1) * 4;
        const __half* sh = qkvh + rowbase + (size_t)(q0 + r) * (3 * E_) + cg * 8;
        const uint32_t d = r * QP * 2 + cg * 16;
#pragma unroll
        for (int j = 0; j < 4; j++)
            cp16(sQh + d + j * 16, sh + j * 8);
    }

    auto load_kv = [&](int kt, int st) {
        const int r  = tid >> 2;
        const int cg = (tid & 3) * 2;
        const size_t grow = rowbase + (size_t)(kt * 64 + r) * (3 * E_);
        const uint32_t sd = sSt + st * AST_BYTES;
        const uint32_t d  = r * QP * 2 + cg * 16;
#pragma unroll
        for (int j = 0; j < 2; j++) {
            cp16(sd + 0 * QTILE_B + d + j * 16, qkvh + grow + HD_     + cg * 8 + j * 8);
            cp16(sd + 1 * QTILE_B + d + j * 16, qkvh + grow + 2 * HD_ + cg * 8 + j * 8);
        }
    };
    load_kv(0, 0);
    CP_COMMIT();

    float oacc[8][4];
#pragma unroll
    for (int j = 0; j < 8; j++)
#pragma unroll
        for (int r = 0; r < 4; r++) oacc[j][r] = 0.f;
    float m0 = -1e30f, m1 = -1e30f, l0 = 0.f, l1 = 0.f;

    const uint32_t aoff = ((wid * 16 + (g & 1) * 8 + rig) * QP + (g >> 1) * 8) * 2;
    const uint32_t koff = (((g >> 1) * 8 + rig) * QP + (g & 1) * 8) * 2;
    const uint32_t voff = (((g & 1) * 8 + rig) * QP + (g >> 1) * 8) * 2;

    const int NT = S_ / 64;
    for (int kt = 0; kt < NT; kt++) {
        CP_WAIT(0);
        __syncthreads();
        if (kt + 1 < NT) { load_kv(kt + 1, (kt + 1) & 1); CP_COMMIT(); }

        const uint32_t st  = sSt + (kt & 1) * AST_BYTES;
        const uint32_t sKh = st;
        const uint32_t sV  = st + QTILE_B;

        // S = Qh Kh^T
        float sacc[8][4];
#pragma unroll
        for (int j = 0; j < 8; j++)
#pragma unroll
            for (int r = 0; r < 4; r++) sacc[j][r] = 0.f;

#pragma unroll
        for (int t = 0; t < 4; t++) {
            uint32_t qhf[4];
            ldsm4(qhf, sQh + aoff + t * 32);
#pragma unroll
            for (int np = 0; np < 4; np++) {
                uint32_t kh[4];
                ldsm4(kh, sKh + koff + (np * 16 * QP + t * 16) * 2);
#pragma unroll
                for (int jj = 0; jj < 2; jj++) {
                    const int j = np * 2 + jj;
                    mma16816(sacc[j], qhf, kh[jj * 2], kh[jj * 2 + 1]);
                }
            }
        }

        // online softmax (log2 domain)
        float mx0 = -1e30f, mx1 = -1e30f;
#pragma unroll
        for (int j = 0; j < 8; j++) {
            mx0 = fmaxf(mx0, fmaxf(sacc[j][0], sacc[j][1]));
            mx1 = fmaxf(mx1, fmaxf(sacc[j][2], sacc[j][3]));
        }
        mx0 = fmaxf(mx0, __shfl_xor_sync(0xffffffffu, mx0, 1));
        mx0 = fmaxf(mx0, __shfl_xor_sync(0xffffffffu, mx0, 2));
        mx1 = fmaxf(mx1, __shfl_xor_sync(0xffffffffu, mx1, 1));
        mx1 = fmaxf(mx1, __shfl_xor_sync(0xffffffffu, mx1, 2));

        const float m0n = fmaxf(m0, mx0);
        const float m1n = fmaxf(m1, mx1);
        const float al0 = exp2f(m0 - m0n);
        const float al1 = exp2f(m1 - m1n);
        m0 = m0n; m1 = m1n;

        uint32_t aPh[4][4];
        float ps0 = 0.f, ps1 = 0.f;
#pragma unroll
        for (int j = 0; j < 8; j++) {
            const float p0 = exp2f(sacc[j][0] - m0);
            const float p1 = exp2f(sacc[j][1] - m0);
            const float p2 = exp2f(sacc[j][2] - m1);
            const float p3 = exp2f(sacc[j][3] - m1);
            ps0 += p0 + p1; ps1 += p2 + p3;
            const int t = j >> 1, s = (j & 1) * 2;
            aPh[t][s]     = packh2f(p0, p1);
            aPh[t][s + 1] = packh2f(p2, p3);
        }
        ps0 += __shfl_xor_sync(0xffffffffu, ps0, 1);
        ps0 += __shfl_xor_sync(0xffffffffu, ps0, 2);
        ps1 += __shfl_xor_sync(0xffffffffu, ps1, 1);
        ps1 += __shfl_xor_sync(0xffffffffu, ps1, 2);
        l0 = l0 * al0 + ps0;
        l1 = l1 * al1 + ps1;

#pragma unroll
        for (int j = 0; j < 8; j++) {
            oacc[j][0] *= al0; oacc[j][1] *= al0;
            oacc[j][2] *= al1; oacc[j][3] *= al1;
        }

        // O += Ph V
#pragma unroll
        for (int t = 0; t < 4; t++) {
#pragma unroll
            for (int dp = 0; dp < 4; dp++) {
                uint32_t vf[4];
                ldsm4t(vf, sV + voff + (t * 16 * QP + dp * 16) * 2);
#pragma unroll
                for (int jj = 0; jj < 2; jj++) {
                    const int jd = dp * 2 + jj;
                    mma16816(oacc[jd], aPh[t], vf[jj * 2], vf[jj * 2 + 1]);
                }
            }
        }
    }

    const float li0 = 1.0f / l0;
    const float li1 = 1.0f / l1;
    const int r0 = q0 + wid * 16 + (lane >> 2);
    const int dcol = (lane & 3) * 2;
#pragma unroll
    for (int j = 0; j < 8; j++) {
        const size_t o0 = ((size_t)b * S_ + r0) * E_ + h * HD_ + j * 8 + dcol;
        const size_t o1 = o0 + 8 * E_;
        *(__half2*)(ctxh + o0) = __floats2half2_rn(oacc[j][0] * li0, oacc[j][1] * li0);
        *(__half2*)(ctxh + o1) = __floats2half2_rn(oacc[j][2] * li1, oacc[j][3] * li1);
    }
}

// ============================================================================
// Fused residual-add + LayerNorm; optional fp16 (hi only) emission
// ============================================================================
template<int EMIT>
__global__ __launch_bounds__(256)
void add_ln_kernel(const float* __restrict__ x, const float* __restrict__ y,
                   const float* __restrict__ g, const float* __restrict__ beta,
                   float* __restrict__ out, __half* __restrict__ oh) {
    __shared__ float red1[8], red2[8];
    __shared__ float s_mean, s_rstd;
    const int row = blockIdx.x;
    const int tid = threadIdx.x;

    const float4 xv = ((const float4*)(x + (size_t)row * E_))[tid];
    const float4 yv = ((const float4*)(y + (size_t)row * E_))[tid];
    float v0 = xv.x + yv.x, v1 = xv.y + yv.y, v2 = xv.z + yv.z, v3 = xv.w + yv.w;

    float s  = v0 + v1 + v2 + v3;
    float ss = v0 * v0 + v1 * v1 + v2 * v2 + v3 * v3;
#pragma unroll
    for (int o = 16; o > 0; o >>= 1) {
        s  += __shfl_down_sync(0xffffffffu, s, o);
        ss += __shfl_down_sync(0xffffffffu, ss, o);
    }
    const int warp = tid >> 5, lane = tid & 31;
    if (lane == 0) { red1[warp] = s; red2[warp] = ss; }
    __syncthreads();
    if (tid == 0) {
        float ts = 0.f, tss = 0.f;
#pragma unroll
        for (int w = 0; w < 8; w++) { ts += red1[w]; tss += red2[w]; }
        float mean = ts * (1.0f / E_);
        float var  = tss * (1.0f / E_) - mean * mean;
        s_mean = mean;
        s_rstd = rsqrtf(var + 1e-5f);
    }
    __syncthreads();
    const float mean = s_mean, rstd = s_rstd;

    const float4 gv = ((const float4*)g)[tid];
    const float4 bv = ((const float4*)beta)[tid];
    float4 o;
    o.x = (v0 - mean) * rstd * gv.x + bv.x;
    o.y = (v1 - mean) * rstd * gv.y + bv.y;
    o.z = (v2 - mean) * rstd * gv.z + bv.z;
    o.w = (v3 - mean) * rstd * gv.w + bv.w;
    ((float4*)(out + (size_t)row * E_))[tid] = o;
    if (EMIT) {
        const size_t off = (size_t)row * E_ + tid * 4;
        *(__half2*)(oh + off)     = __floats2half2_rn(o.x, o.y);
        *(__half2*)(oh + off + 2) = __floats2half2_rn(o.z, o.w);
    }
}

// ============================================================================
// Launch
// ============================================================================
extern "C" void kernel_launch(void* const* d_in, const int* in_sizes, int n_in,
                              void* d_out, int out_size) {
    const float* x     = (const float*)d_in[0];
    const float* w_qkv = (const float*)d_in[1];
    const float* b_qkv = (const float*)d_in[2];
    const float* w_out = (const float*)d_in[3];
    const float* b_out = (const float*)d_in[4];
    const float* g1    = (const float*)d_in[5];
    const float* beta1 = (const float*)d_in[6];
    const float* g2    = (const float*)d_in[7];
    const float* beta2 = (const float*)d_in[8];
    const float* w1    = (const float*)d_in[9];
    const float* bf1   = (const float*)d_in[10];
    const float* w2    = (const float*)d_in[11];
    const float* bf2   = (const float*)d_in[12];
    float* out = (float*)d_out;

    float *tmp, *x1;
    cudaGetSymbolAddress((void**)&tmp,  g_tmp);
    cudaGetSymbolAddress((void**)&x1,   g_x1);

    __half *xh, *qkvh, *ctxh, *x1h, *hh;
    __half *wqkvh, *wouth, *w1h, *w2h;
    cudaGetSymbolAddress((void**)&xh, g_xh);
    cudaGetSymbolAddress((void**)&qkvh, g_qkvh);
    cudaGetSymbolAddress((void**)&ctxh, g_ctxh);
    cudaGetSymbolAddress((void**)&x1h, g_x1h);
    cudaGetSymbolAddress((void**)&hh, g_hh);
    cudaGetSymbolAddress((void**)&wqkvh, g_wqkvh);
    cudaGetSymbolAddress((void**)&wouth, g_wouth);
    cudaGetSymbolAddress((void**)&w1h, g_w1h);
    cudaGetSymbolAddress((void**)&w2h, g_w2h);

    cudaFuncSetAttribute(attn_tc, cudaFuncAttributeMaxDynamicSharedMemorySize, ASMEM_TOTAL);
    cudaFuncSetAttribute(mma_gemm<0,0,0>, cudaFuncAttributeMaxDynamicSharedMemorySize, GSMEM_TOTAL);
    cudaFuncSetAttribute(mma_gemm<0,2,1>, cudaFuncAttributeMaxDynamicSharedMemorySize, GSMEM_TOTAL);
    cudaFuncSetAttribute(mma_gemm<1,2,0>, cudaFuncAttributeMaxDynamicSharedMemorySize, GSMEM_TOTAL);

    dim3 thr(256);

    // 0: weights + x -> fp16
    conv_kernel<<<16384, thr>>>(w_qkv, w_out, w1, w2, x,
                                wqkvh, wouth, w1h, w2h, xh);

    // 1: qkv = x @ w_qkv^T + b_qkv -> fp16 hi (Q pre-scaled)
    mma_gemm<0,2,1><<<dim3(3 * E_ / 128, M_ / 128), thr, GSMEM_TOTAL>>>(
        xh, wqkvh, b_qkv, nullptr, qkvh, M_, 3 * E_, E_);

    // 2: flash attention -> ctx (fp16 hi)
    attn_tc<<<dim3(S_ / 128, H_, B_), thr, ASMEM_TOTAL>>>(qkvh, ctxh);

    // 3: out-proj (fp32 out)
    mma_gemm<0,0,0><<<dim3(E_ / 128, M_ / 128), thr, GSMEM_TOTAL>>>(
        ctxh, wouth, b_out, tmp, nullptr, M_, E_, E_);

    // 4: residual + LN -> x1 (+ fp16)
    add_ln_kernel<1><<<M_, thr>>>(x, tmp, g1, beta1, x1, x1h);

    // 5: h = gelu(x1 @ w1^T + bf1) -> fp16
    mma_gemm<1,2,0><<<dim3(FF_ / 128, M_ / 128), thr, GSMEM_TOTAL>>>(
        x1h, w1h, bf1, nullptr, hh, M_, FF_, E_);

    // 6: ffn2 (fp32 out)
    mma_gemm<0,0,0><<<dim3(E_ / 128, M_ / 128), thr, GSMEM_TOTAL>>>(
        hh, w2h, bf2, tmp, nullptr, M_, E_, FF_);

    // 7: residual + LN -> out
    add_ln_kernel<0><<<M_, thr>>>(x1, tmp, g2, beta2, out, nullptr);
}